// round 1
// baseline (speedup 1.0000x reference)
#include <cuda_runtime.h>
#include <cuda_fp16.h>
#include <math.h>
#include <stdint.h>

#define T_TOK 4096
#define H_DIM 1024
#define E_NUM 8
#define F_DIM 4096

// ---------------- scratch (static device globals; no allocations) ----------
__device__ int    g_cnt[E_NUM];
__device__ int    g_off[E_NUM];
__device__ int    g_tok[E_NUM * T_TOK];
__device__ float  g_gate[E_NUM * T_TOK];
__device__ __half g_xh[(size_t)T_TOK * H_DIM];           // x in fp16 (8 MB)
__device__ __half g_h[(size_t)T_TOK * 2 * F_DIM];        // routed hidden (64 MB)

// ---------------- small helpers -------------------------------------------
__device__ __forceinline__ float gelu_f(float v) {
    return 0.5f * v * (1.0f + erff(v * 0.70710678118654752440f));
}

__device__ __forceinline__ void mma16816(float* c, const unsigned* a, const unsigned* b) {
    asm volatile(
        "mma.sync.aligned.m16n8k16.row.col.f32.f16.f16.f32 "
        "{%0,%1,%2,%3}, {%4,%5,%6,%7}, {%8,%9}, {%0,%1,%2,%3};\n"
        : "+f"(c[0]), "+f"(c[1]), "+f"(c[2]), "+f"(c[3])
        : "r"(a[0]), "r"(a[1]), "r"(a[2]), "r"(a[3]), "r"(b[0]), "r"(b[1]));
}

__device__ __forceinline__ void ldsm_x4(unsigned* r, uint32_t addr) {
    asm volatile("ldmatrix.sync.aligned.m8n8.x4.shared.b16 {%0,%1,%2,%3}, [%4];\n"
                 : "=r"(r[0]), "=r"(r[1]), "=r"(r[2]), "=r"(r[3]) : "r"(addr));
}
__device__ __forceinline__ void ldsm_x4t(unsigned* r, uint32_t addr) {
    asm volatile("ldmatrix.sync.aligned.m8n8.x4.trans.shared.b16 {%0,%1,%2,%3}, [%4];\n"
                 : "=r"(r[0]), "=r"(r[1]), "=r"(r[2]), "=r"(r[3]) : "r"(addr));
}

// ---------------- kernel 0: zero out + counters, convert x -> fp16 --------
__global__ void prep_kernel(const float* __restrict__ x, float* __restrict__ out) {
    int i = blockIdx.x * blockDim.x + threadIdx.x;
    if (i < T_TOK * H_DIM) {
        g_xh[i] = __float2half(x[i]);
        out[i]  = 0.0f;
    }
    if (i < E_NUM) g_cnt[i] = 0;
}

// ---------------- kernel 1: router (fp32), top-2, softmax, scatter --------
__global__ void router_kernel(const float* __restrict__ x, const float* __restrict__ Wr) {
    int gwarp = (blockIdx.x * blockDim.x + threadIdx.x) >> 5;
    int lane  = threadIdx.x & 31;
    if (gwarp >= T_TOK) return;
    const float* xr = x + (size_t)gwarp * H_DIM;
    float xv[32];
#pragma unroll
    for (int i = 0; i < 32; i++) xv[i] = xr[lane + 32 * i];

    float logits[E_NUM];
#pragma unroll
    for (int e = 0; e < E_NUM; e++) {
        const float* w = Wr + e * H_DIM;
        float s = 0.0f;
#pragma unroll
        for (int i = 0; i < 32; i++) s += xv[i] * w[lane + 32 * i];
#pragma unroll
        for (int o = 16; o > 0; o >>= 1) s += __shfl_xor_sync(0xffffffffu, s, o);
        logits[e] = s;
    }
    if (lane == 0) {
        int i0 = 0; float v0 = logits[0];
#pragma unroll
        for (int e = 1; e < E_NUM; e++) if (logits[e] > v0) { v0 = logits[e]; i0 = e; }
        int i1 = -1; float v1 = -1e30f;
#pragma unroll
        for (int e = 0; e < E_NUM; e++) if (e != i0 && logits[e] > v1) { v1 = logits[e]; i1 = e; }
        float ex = expf(v1 - v0);               // <= 0 exponent
        float p0 = 1.0f / (1.0f + ex);
        float p1 = ex / (1.0f + ex);
        int pos0 = atomicAdd(&g_cnt[i0], 1);
        g_tok[i0 * T_TOK + pos0] = gwarp;  g_gate[i0 * T_TOK + pos0] = p0;
        int pos1 = atomicAdd(&g_cnt[i1], 1);
        g_tok[i1 * T_TOK + pos1] = gwarp;  g_gate[i1 * T_TOK + pos1] = p1;
    }
}

// ---------------- kernel 2: exclusive scan of 8 counts --------------------
__global__ void scan_kernel() {
    if (threadIdx.x == 0 && blockIdx.x == 0) {
        int a = 0;
#pragma unroll
        for (int e = 0; e < E_NUM; e++) { g_off[e] = a; a += g_cnt[e]; }
    }
}

// ---------------- GEMM1: h = gelu(x @ W1[e] + b1[e]) ----------------------
// grid: (F/128, 32, E), block 256. BM=128 BN=128 BK=32.
__global__ __launch_bounds__(256) void gemm1_kernel(const float* __restrict__ W1,
                                                    const float* __restrict__ b1) {
    const int e   = blockIdx.z;
    const int cnt = g_cnt[e];
    const int m0  = blockIdx.y * 128;
    if (m0 >= cnt) return;
    const int n0   = blockIdx.x * 128;
    const int roff = g_off[e];
    const float* W = W1 + (size_t)e * H_DIM * F_DIM;

    const int tid = threadIdx.x, lane = tid & 31, warp = tid >> 5;
    const int wm = warp & 3, wn = warp >> 2;

    __shared__ __half As[128][40];   // +8 pad: conflict-free ldmatrix
    __shared__ __half Bs[32][136];
    __shared__ int    toks[128];

    if (tid < 128) {
        int r = m0 + tid;
        toks[tid] = (r < cnt) ? g_tok[e * T_TOK + r] : -1;
    }
    __syncthreads();

    float acc[2][8][4];
#pragma unroll
    for (int a = 0; a < 2; a++)
#pragma unroll
        for (int b = 0; b < 8; b++)
#pragma unroll
            for (int c = 0; c < 4; c++) acc[a][b][c] = 0.0f;

    uint32_t asb = (uint32_t)__cvta_generic_to_shared(&As[0][0]);
    uint32_t bsb = (uint32_t)__cvta_generic_to_shared(&Bs[0][0]);

    for (int k0 = 0; k0 < H_DIM; k0 += 32) {
        // A: 128 rows x 32 halfs (gathered token rows)
#pragma unroll
        for (int p = 0; p < 2; p++) {
            int idx = p * 256 + tid;
            int r = idx >> 2, c = idx & 3;
            int tok = toks[r];
            uint4 v = make_uint4(0u, 0u, 0u, 0u);
            if (tok >= 0)
                v = *(const uint4*)(g_xh + (size_t)tok * H_DIM + k0 + c * 8);
            *(uint4*)(&As[r][c * 8]) = v;
        }
        // B: 32 rows(k) x 128 cols(n), fp32 -> fp16 inline
#pragma unroll
        for (int p = 0; p < 4; p++) {
            int idx = p * 256 + tid;
            int kr = idx >> 5, c4 = idx & 31;
            float4 v = *(const float4*)(W + (size_t)(k0 + kr) * F_DIM + n0 + c4 * 4);
            *(__half2*)(&Bs[kr][c4 * 4])     = __floats2half2_rn(v.x, v.y);
            *(__half2*)(&Bs[kr][c4 * 4 + 2]) = __floats2half2_rn(v.z, v.w);
        }
        __syncthreads();

#pragma unroll
        for (int ks = 0; ks < 2; ks++) {
            unsigned af[2][4], bf[4][4];
#pragma unroll
            for (int mi = 0; mi < 2; mi++) {
                int row = wm * 32 + mi * 16 + (lane & 15);
                int col = ks * 16 + (lane >> 4) * 8;
                ldsm_x4(af[mi], asb + (uint32_t)(row * 40 + col) * 2u);
            }
#pragma unroll
            for (int nb = 0; nb < 4; nb++) {
                int kr  = ks * 16 + (lane & 15);
                int col = wn * 64 + nb * 16 + (lane >> 4) * 8;
                ldsm_x4t(bf[nb], bsb + (uint32_t)(kr * 136 + col) * 2u);
            }
#pragma unroll
            for (int mi = 0; mi < 2; mi++)
#pragma unroll
                for (int nb = 0; nb < 4; nb++) {
                    mma16816(acc[mi][nb * 2],     af[mi], &bf[nb][0]);
                    mma16816(acc[mi][nb * 2 + 1], af[mi], &bf[nb][2]);
                }
        }
        __syncthreads();
    }

    const float* be = b1 + e * F_DIM;
#pragma unroll
    for (int mi = 0; mi < 2; mi++) {
        int rbase = wm * 32 + mi * 16 + (lane >> 2);
#pragma unroll
        for (int nf = 0; nf < 8; nf++) {
            int cbase = wn * 64 + nf * 8 + (lane & 3) * 2;
#pragma unroll
            for (int h = 0; h < 2; h++) {
                int r = rbase + h * 8;
                int gm = m0 + r;
                if (gm < cnt) {
                    float v0 = gelu_f(acc[mi][nf][h * 2]     + be[n0 + cbase]);
                    float v1 = gelu_f(acc[mi][nf][h * 2 + 1] + be[n0 + cbase + 1]);
                    *(__half2*)(g_h + (size_t)(roff + gm) * F_DIM + n0 + cbase) =
                        __floats2half2_rn(v0, v1);
                }
            }
        }
    }
}

// ---------------- GEMM2: out[tok] += gate * (h @ W2[e] + b2[e]) -----------
// grid: (H/128, 32, E), block 256.
__global__ __launch_bounds__(256) void gemm2_kernel(const float* __restrict__ W2,
                                                    const float* __restrict__ b2,
                                                    float* __restrict__ out) {
    const int e   = blockIdx.z;
    const int cnt = g_cnt[e];
    const int m0  = blockIdx.y * 128;
    if (m0 >= cnt) return;
    const int n0   = blockIdx.x * 128;
    const int roff = g_off[e];
    const float* W = W2 + (size_t)e * F_DIM * H_DIM;

    const int tid = threadIdx.x, lane = tid & 31, warp = tid >> 5;
    const int wm = warp & 3, wn = warp >> 2;

    __shared__ __half As[128][40];
    __shared__ __half Bs[32][136];
    __shared__ int    toks[128];
    __shared__ float  gts[128];

    if (tid < 128) {
        int r = m0 + tid;
        if (r < cnt) { toks[tid] = g_tok[e * T_TOK + r]; gts[tid] = g_gate[e * T_TOK + r]; }
        else         { toks[tid] = 0;                    gts[tid] = 0.0f; }
    }
    __syncthreads();

    float acc[2][8][4];
#pragma unroll
    for (int a = 0; a < 2; a++)
#pragma unroll
        for (int b = 0; b < 8; b++)
#pragma unroll
            for (int c = 0; c < 4; c++) acc[a][b][c] = 0.0f;

    uint32_t asb = (uint32_t)__cvta_generic_to_shared(&As[0][0]);
    uint32_t bsb = (uint32_t)__cvta_generic_to_shared(&Bs[0][0]);

    for (int k0 = 0; k0 < F_DIM; k0 += 32) {
        // A: routed hidden rows (fp16 already), clamp OOB rows to row 0 of this expert
#pragma unroll
        for (int p = 0; p < 2; p++) {
            int idx = p * 256 + tid;
            int r = idx >> 2, c = idx & 3;
            int gm = m0 + r;
            size_t srow = (size_t)roff + (gm < cnt ? gm : 0);
            *(uint4*)(&As[r][c * 8]) =
                *(const uint4*)(g_h + srow * F_DIM + k0 + c * 8);
        }
        // B: W2 tile 32(k) x 128(n) fp32 -> fp16
#pragma unroll
        for (int p = 0; p < 4; p++) {
            int idx = p * 256 + tid;
            int kr = idx >> 5, c4 = idx & 31;
            float4 v = *(const float4*)(W + (size_t)(k0 + kr) * H_DIM + n0 + c4 * 4);
            *(__half2*)(&Bs[kr][c4 * 4])     = __floats2half2_rn(v.x, v.y);
            *(__half2*)(&Bs[kr][c4 * 4 + 2]) = __floats2half2_rn(v.z, v.w);
        }
        __syncthreads();

#pragma unroll
        for (int ks = 0; ks < 2; ks++) {
            unsigned af[2][4], bf[4][4];
#pragma unroll
            for (int mi = 0; mi < 2; mi++) {
                int row = wm * 32 + mi * 16 + (lane & 15);
                int col = ks * 16 + (lane >> 4) * 8;
                ldsm_x4(af[mi], asb + (uint32_t)(row * 40 + col) * 2u);
            }
#pragma unroll
            for (int nb = 0; nb < 4; nb++) {
                int kr  = ks * 16 + (lane & 15);
                int col = wn * 64 + nb * 16 + (lane >> 4) * 8;
                ldsm_x4t(bf[nb], bsb + (uint32_t)(kr * 136 + col) * 2u);
            }
#pragma unroll
            for (int mi = 0; mi < 2; mi++)
#pragma unroll
                for (int nb = 0; nb < 4; nb++) {
                    mma16816(acc[mi][nb * 2],     af[mi], &bf[nb][0]);
                    mma16816(acc[mi][nb * 2 + 1], af[mi], &bf[nb][2]);
                }
        }
        __syncthreads();
    }

    const float* be = b2 + e * H_DIM;
#pragma unroll
    for (int mi = 0; mi < 2; mi++) {
        int rbase = wm * 32 + mi * 16 + (lane >> 2);
#pragma unroll
        for (int nf = 0; nf < 8; nf++) {
            int cbase = wn * 64 + nf * 8 + (lane & 3) * 2;
#pragma unroll
            for (int h = 0; h < 2; h++) {
                int r = rbase + h * 8;
                int gm = m0 + r;
                if (gm < cnt) {
                    int   tok = toks[r];
                    float g   = gts[r];
                    float v0  = acc[mi][nf][h * 2]     + be[n0 + cbase];
                    float v1  = acc[mi][nf][h * 2 + 1] + be[n0 + cbase + 1];
                    atomicAdd(&out[(size_t)tok * H_DIM + n0 + cbase],     g * v0);
                    atomicAdd(&out[(size_t)tok * H_DIM + n0 + cbase + 1], g * v1);
                }
            }
        }
    }
}

// ---------------- launch ---------------------------------------------------
extern "C" void kernel_launch(void* const* d_in, const int* in_sizes, int n_in,
                              void* d_out, int out_size) {
    const float* x  = (const float*)d_in[0];
    const float* Wr = (const float*)d_in[1];
    const float* W1 = (const float*)d_in[2];
    const float* b1 = (const float*)d_in[3];
    const float* W2 = (const float*)d_in[4];
    const float* b2 = (const float*)d_in[5];
    float* out = (float*)d_out;

    prep_kernel<<<(T_TOK * H_DIM + 255) / 256, 256>>>(x, out);
    router_kernel<<<T_TOK / 8, 256>>>(x, Wr);
    scan_kernel<<<1, 32>>>();
    gemm1_kernel<<<dim3(F_DIM / 128, 32, E_NUM), 256>>>(W1, b1);
    gemm2_kernel<<<dim3(H_DIM / 128, 32, E_NUM), 256>>>(W2, b2, out);
}

// round 2
// speedup vs baseline: 1.2850x; 1.2850x over previous
#include <cuda_runtime.h>
#include <cuda_fp16.h>
#include <math.h>
#include <stdint.h>

#define T_TOK 4096
#define H_DIM 1024
#define E_NUM 8
#define F_DIM 4096

#define A_ST 5120            // 128*40 halfs per A stage
#define B_ST 4352            // 32*136 halfs per B stage
#define STAGES 3
#define SMEM_BYTES ((STAGES * (A_ST + B_ST)) * 2)   // 56832

// ---------------- scratch (static device globals; no allocations) ----------
__device__ int    g_cnt[E_NUM];
__device__ int    g_off[E_NUM];
__device__ int    g_tok[E_NUM * T_TOK];
__device__ float  g_gate[E_NUM * T_TOK];
__device__ __half g_xh[(size_t)T_TOK * H_DIM];             // x fp16 (8 MB)
__device__ __half g_h[(size_t)T_TOK * 2 * F_DIM];          // routed hidden (64 MB)
__device__ __half g_w1[(size_t)E_NUM * H_DIM * F_DIM];     // W1 fp16 (64 MB)
__device__ __half g_w2[(size_t)E_NUM * F_DIM * H_DIM];     // W2 fp16 (64 MB)

// ---------------- helpers -------------------------------------------------
__device__ __forceinline__ float gelu_f(float v) {
    return 0.5f * v * (1.0f + erff(v * 0.70710678118654752440f));
}

__device__ __forceinline__ void mma16816(float* c, const unsigned* a, const unsigned* b) {
    asm volatile(
        "mma.sync.aligned.m16n8k16.row.col.f32.f16.f16.f32 "
        "{%0,%1,%2,%3}, {%4,%5,%6,%7}, {%8,%9}, {%0,%1,%2,%3};\n"
        : "+f"(c[0]), "+f"(c[1]), "+f"(c[2]), "+f"(c[3])
        : "r"(a[0]), "r"(a[1]), "r"(a[2]), "r"(a[3]), "r"(b[0]), "r"(b[1]));
}
__device__ __forceinline__ void ldsm_x4(unsigned* r, uint32_t addr) {
    asm volatile("ldmatrix.sync.aligned.m8n8.x4.shared.b16 {%0,%1,%2,%3}, [%4];\n"
                 : "=r"(r[0]), "=r"(r[1]), "=r"(r[2]), "=r"(r[3]) : "r"(addr));
}
__device__ __forceinline__ void ldsm_x4t(unsigned* r, uint32_t addr) {
    asm volatile("ldmatrix.sync.aligned.m8n8.x4.trans.shared.b16 {%0,%1,%2,%3}, [%4];\n"
                 : "=r"(r[0]), "=r"(r[1]), "=r"(r[2]), "=r"(r[3]) : "r"(addr));
}
__device__ __forceinline__ void cpa16(uint32_t dst, const void* src) {
    asm volatile("cp.async.cg.shared.global [%0], [%1], 16;\n" :: "r"(dst), "l"(src));
}
__device__ __forceinline__ void cpa16p(uint32_t dst, const void* src, bool valid) {
    int sz = valid ? 16 : 0;   // zero-fill when invalid
    asm volatile("cp.async.cg.shared.global [%0], [%1], 16, %2;\n"
                 :: "r"(dst), "l"(src), "r"(sz));
}
__device__ __forceinline__ void cpa_commit() { asm volatile("cp.async.commit_group;\n"); }
__device__ __forceinline__ void cpa_wait1()  { asm volatile("cp.async.wait_group 1;\n"); }

// ---------------- kernel 0: zero out + counters, convert x -> fp16 --------
__global__ void prep_kernel(const float* __restrict__ x, float* __restrict__ out) {
    int i = blockIdx.x * blockDim.x + threadIdx.x;
    if (i < T_TOK * H_DIM) {
        g_xh[i] = __float2half(x[i]);
        out[i]  = 0.0f;
    }
    if (i < E_NUM) g_cnt[i] = 0;
}

// ---------------- kernel 0b: convert W1/W2 -> fp16 ------------------------
__global__ void convw_kernel(const float* __restrict__ W1, const float* __restrict__ W2) {
    const size_t N = (size_t)E_NUM * H_DIM * F_DIM;   // 33.55M per array
    size_t base = ((size_t)blockIdx.x * blockDim.x + threadIdx.x) * 8;
    if (base >= N) return;
    const float* src = blockIdx.y ? W2 : W1;
    __half* dst      = blockIdx.y ? g_w2 : g_w1;
    float4 a = *(const float4*)(src + base);
    float4 b = *(const float4*)(src + base + 4);
    __half2 h[4];
    h[0] = __floats2half2_rn(a.x, a.y);
    h[1] = __floats2half2_rn(a.z, a.w);
    h[2] = __floats2half2_rn(b.x, b.y);
    h[3] = __floats2half2_rn(b.z, b.w);
    *(uint4*)(dst + base) = *(uint4*)h;
}

// ---------------- kernel 1: router --------------------------------------
__global__ void router_kernel(const float* __restrict__ x, const float* __restrict__ Wr) {
    int gwarp = (blockIdx.x * blockDim.x + threadIdx.x) >> 5;
    int lane  = threadIdx.x & 31;
    if (gwarp >= T_TOK) return;
    const float* xr = x + (size_t)gwarp * H_DIM;
    float xv[32];
#pragma unroll
    for (int i = 0; i < 32; i++) xv[i] = xr[lane + 32 * i];

    float logits[E_NUM];
#pragma unroll
    for (int e = 0; e < E_NUM; e++) {
        const float* w = Wr + e * H_DIM;
        float s = 0.0f;
#pragma unroll
        for (int i = 0; i < 32; i++) s += xv[i] * w[lane + 32 * i];
#pragma unroll
        for (int o = 16; o > 0; o >>= 1) s += __shfl_xor_sync(0xffffffffu, s, o);
        logits[e] = s;
    }
    if (lane == 0) {
        int i0 = 0; float v0 = logits[0];
#pragma unroll
        for (int e = 1; e < E_NUM; e++) if (logits[e] > v0) { v0 = logits[e]; i0 = e; }
        int i1 = -1; float v1 = -1e30f;
#pragma unroll
        for (int e = 0; e < E_NUM; e++) if (e != i0 && logits[e] > v1) { v1 = logits[e]; i1 = e; }
        float ex = expf(v1 - v0);
        float p0 = 1.0f / (1.0f + ex);
        float p1 = ex / (1.0f + ex);
        int pos0 = atomicAdd(&g_cnt[i0], 1);
        g_tok[i0 * T_TOK + pos0] = gwarp;  g_gate[i0 * T_TOK + pos0] = p0;
        int pos1 = atomicAdd(&g_cnt[i1], 1);
        g_tok[i1 * T_TOK + pos1] = gwarp;  g_gate[i1 * T_TOK + pos1] = p1;
    }
}

// ---------------- kernel 2: scan ------------------------------------------
__global__ void scan_kernel() {
    if (threadIdx.x == 0 && blockIdx.x == 0) {
        int a = 0;
#pragma unroll
        for (int e = 0; e < E_NUM; e++) { g_off[e] = a; a += g_cnt[e]; }
    }
}

// ---------------- GEMM1: h = gelu(x @ W1[e] + b1[e]) ----------------------
// grid: (F/128, 32, E), block 256. BM=128 BN=128 BK=32, 3-stage cp.async.
__global__ __launch_bounds__(256, 2) void gemm1_kernel(const float* __restrict__ b1) {
    const int e   = blockIdx.z;
    const int cnt = g_cnt[e];
    const int m0  = blockIdx.y * 128;
    if (m0 >= cnt) return;
    const int n0   = blockIdx.x * 128;
    const int roff = g_off[e];
    const __half* W = g_w1 + (size_t)e * H_DIM * F_DIM;

    const int tid = threadIdx.x, lane = tid & 31, warp = tid >> 5;
    const int wm = warp & 3, wn = warp >> 2;

    extern __shared__ __half sh[];
    __shared__ int toks[128];

    if (tid < 128) {
        int r = m0 + tid;
        toks[tid] = (r < cnt) ? g_tok[e * T_TOK + r] : -1;
    }
    __syncthreads();

    uint32_t asb = (uint32_t)__cvta_generic_to_shared(sh);
    uint32_t bsb = (uint32_t)__cvta_generic_to_shared(sh + STAGES * A_ST);

    // tile loader: tile kt (k0=kt*32) into stage s
    auto load_tile = [&](int kt, int s) {
        int k0 = kt * 32;
#pragma unroll
        for (int p = 0; p < 2; p++) {   // A: 128x32 halfs, 512 16B chunks
            int idx = p * 256 + tid;
            int r = idx >> 2, c = idx & 3;
            int tok = toks[r];
            const void* src = (tok >= 0) ? (const void*)(g_xh + (size_t)tok * H_DIM + k0 + c * 8)
                                         : (const void*)g_xh;
            cpa16p(asb + (uint32_t)(s * A_ST + r * 40 + c * 8) * 2u, src, tok >= 0);
        }
#pragma unroll
        for (int p = 0; p < 2; p++) {   // B: 32x128 halfs
            int idx = p * 256 + tid;
            int kr = idx >> 4, c = idx & 15;
            cpa16(bsb + (uint32_t)(s * B_ST + kr * 136 + c * 8) * 2u,
                  W + (size_t)(k0 + kr) * F_DIM + n0 + c * 8);
        }
    };

    float acc[2][8][4];
#pragma unroll
    for (int a = 0; a < 2; a++)
#pragma unroll
        for (int b = 0; b < 8; b++)
#pragma unroll
            for (int c = 0; c < 4; c++) acc[a][b][c] = 0.0f;

    load_tile(0, 0); cpa_commit();
    load_tile(1, 1); cpa_commit();

    const int NT = H_DIM / 32;
    for (int kt = 0; kt < NT; kt++) {
        int s = kt % STAGES;
        cpa_wait1();
        __syncthreads();
        int nk = kt + 2;
        if (nk < NT) load_tile(nk, nk % STAGES);
        cpa_commit();

        uint32_t as = asb + (uint32_t)(s * A_ST) * 2u;
        uint32_t bs = bsb + (uint32_t)(s * B_ST) * 2u;
#pragma unroll
        for (int ks = 0; ks < 2; ks++) {
            unsigned af[2][4], bf[4][4];
#pragma unroll
            for (int mi = 0; mi < 2; mi++) {
                int row = wm * 32 + mi * 16 + (lane & 15);
                int col = ks * 16 + (lane >> 4) * 8;
                ldsm_x4(af[mi], as + (uint32_t)(row * 40 + col) * 2u);
            }
#pragma unroll
            for (int nb = 0; nb < 4; nb++) {
                int kr  = ks * 16 + (lane & 15);
                int col = wn * 64 + nb * 16 + (lane >> 4) * 8;
                ldsm_x4t(bf[nb], bs + (uint32_t)(kr * 136 + col) * 2u);
            }
#pragma unroll
            for (int mi = 0; mi < 2; mi++)
#pragma unroll
                for (int nb = 0; nb < 4; nb++) {
                    mma16816(acc[mi][nb * 2],     af[mi], &bf[nb][0]);
                    mma16816(acc[mi][nb * 2 + 1], af[mi], &bf[nb][2]);
                }
        }
    }

    const float* be = b1 + e * F_DIM;
#pragma unroll
    for (int mi = 0; mi < 2; mi++) {
        int rbase = wm * 32 + mi * 16 + (lane >> 2);
#pragma unroll
        for (int nf = 0; nf < 8; nf++) {
            int cbase = wn * 64 + nf * 8 + (lane & 3) * 2;
#pragma unroll
            for (int h = 0; h < 2; h++) {
                int r = rbase + h * 8;
                int gm = m0 + r;
                if (gm < cnt) {
                    float v0 = gelu_f(acc[mi][nf][h * 2]     + be[n0 + cbase]);
                    float v1 = gelu_f(acc[mi][nf][h * 2 + 1] + be[n0 + cbase + 1]);
                    *(__half2*)(g_h + (size_t)(roff + gm) * F_DIM + n0 + cbase) =
                        __floats2half2_rn(v0, v1);
                }
            }
        }
    }
}

// ---------------- GEMM2: out[tok] += gate * (h @ W2[e] + b2[e]) -----------
// grid: (H/128, 32, E), block 256, 3-stage cp.async.
__global__ __launch_bounds__(256, 2) void gemm2_kernel(const float* __restrict__ b2,
                                                       float* __restrict__ out) {
    const int e   = blockIdx.z;
    const int cnt = g_cnt[e];
    const int m0  = blockIdx.y * 128;
    if (m0 >= cnt) return;
    const int n0   = blockIdx.x * 128;
    const int roff = g_off[e];
    const __half* W = g_w2 + (size_t)e * F_DIM * H_DIM;

    const int tid = threadIdx.x, lane = tid & 31, warp = tid >> 5;
    const int wm = warp & 3, wn = warp >> 2;

    extern __shared__ __half sh[];
    __shared__ int   toks[128];
    __shared__ float gts[128];

    if (tid < 128) {
        int r = m0 + tid;
        if (r < cnt) { toks[tid] = g_tok[e * T_TOK + r]; gts[tid] = g_gate[e * T_TOK + r]; }
        else         { toks[tid] = 0;                    gts[tid] = 0.0f; }
    }
    __syncthreads();

    uint32_t asb = (uint32_t)__cvta_generic_to_shared(sh);
    uint32_t bsb = (uint32_t)__cvta_generic_to_shared(sh + STAGES * A_ST);

    auto load_tile = [&](int kt, int s) {
        int k0 = kt * 32;
#pragma unroll
        for (int p = 0; p < 2; p++) {
            int idx = p * 256 + tid;
            int r = idx >> 2, c = idx & 3;
            int gm = m0 + r;
            size_t srow = (size_t)roff + (gm < cnt ? gm : 0);
            cpa16(asb + (uint32_t)(s * A_ST + r * 40 + c * 8) * 2u,
                  g_h + srow * F_DIM + k0 + c * 8);
        }
#pragma unroll
        for (int p = 0; p < 2; p++) {
            int idx = p * 256 + tid;
            int kr = idx >> 4, c = idx & 15;
            cpa16(bsb + (uint32_t)(s * B_ST + kr * 136 + c * 8) * 2u,
                  W + (size_t)(k0 + kr) * H_DIM + n0 + c * 8);
        }
    };

    float acc[2][8][4];
#pragma unroll
    for (int a = 0; a < 2; a++)
#pragma unroll
        for (int b = 0; b < 8; b++)
#pragma unroll
            for (int c = 0; c < 4; c++) acc[a][b][c] = 0.0f;

    load_tile(0, 0); cpa_commit();
    load_tile(1, 1); cpa_commit();

    const int NT = F_DIM / 32;
    for (int kt = 0; kt < NT; kt++) {
        int s = kt % STAGES;
        cpa_wait1();
        __syncthreads();
        int nk = kt + 2;
        if (nk < NT) load_tile(nk, nk % STAGES);
        cpa_commit();

        uint32_t as = asb + (uint32_t)(s * A_ST) * 2u;
        uint32_t bs = bsb + (uint32_t)(s * B_ST) * 2u;
#pragma unroll
        for (int ks = 0; ks < 2; ks++) {
            unsigned af[2][4], bf[4][4];
#pragma unroll
            for (int mi = 0; mi < 2; mi++) {
                int row = wm * 32 + mi * 16 + (lane & 15);
                int col = ks * 16 + (lane >> 4) * 8;
                ldsm_x4(af[mi], as + (uint32_t)(row * 40 + col) * 2u);
            }
#pragma unroll
            for (int nb = 0; nb < 4; nb++) {
                int kr  = ks * 16 + (lane & 15);
                int col = wn * 64 + nb * 16 + (lane >> 4) * 8;
                ldsm_x4t(bf[nb], bs + (uint32_t)(kr * 136 + col) * 2u);
            }
#pragma unroll
            for (int mi = 0; mi < 2; mi++)
#pragma unroll
                for (int nb = 0; nb < 4; nb++) {
                    mma16816(acc[mi][nb * 2],     af[mi], &bf[nb][0]);
                    mma16816(acc[mi][nb * 2 + 1], af[mi], &bf[nb][2]);
                }
        }
    }

    const float* be = b2 + e * H_DIM;
#pragma unroll
    for (int mi = 0; mi < 2; mi++) {
        int rbase = wm * 32 + mi * 16 + (lane >> 2);
#pragma unroll
        for (int nf = 0; nf < 8; nf++) {
            int cbase = wn * 64 + nf * 8 + (lane & 3) * 2;
#pragma unroll
            for (int h = 0; h < 2; h++) {
                int r = rbase + h * 8;
                int gm = m0 + r;
                if (gm < cnt) {
                    int   tok = toks[r];
                    float g   = gts[r];
                    float v0  = acc[mi][nf][h * 2]     + be[n0 + cbase];
                    float v1  = acc[mi][nf][h * 2 + 1] + be[n0 + cbase + 1];
                    atomicAdd(&out[(size_t)tok * H_DIM + n0 + cbase],     g * v0);
                    atomicAdd(&out[(size_t)tok * H_DIM + n0 + cbase + 1], g * v1);
                }
            }
        }
    }
}

// ---------------- launch ---------------------------------------------------
extern "C" void kernel_launch(void* const* d_in, const int* in_sizes, int n_in,
                              void* d_out, int out_size) {
    const float* x  = (const float*)d_in[0];
    const float* Wr = (const float*)d_in[1];
    const float* W1 = (const float*)d_in[2];
    const float* b1 = (const float*)d_in[3];
    const float* W2 = (const float*)d_in[4];
    const float* b2 = (const float*)d_in[5];
    float* out = (float*)d_out;

    cudaFuncSetAttribute(gemm1_kernel, cudaFuncAttributeMaxDynamicSharedMemorySize, SMEM_BYTES);
    cudaFuncSetAttribute(gemm2_kernel, cudaFuncAttributeMaxDynamicSharedMemorySize, SMEM_BYTES);

    prep_kernel<<<(T_TOK * H_DIM + 255) / 256, 256>>>(x, out);
    convw_kernel<<<dim3(16384, 2), 256>>>(W1, W2);
    router_kernel<<<T_TOK / 8, 256>>>(x, Wr);
    scan_kernel<<<1, 32>>>();
    gemm1_kernel<<<dim3(F_DIM / 128, 32, E_NUM), 256, SMEM_BYTES>>>(b1);
    gemm2_kernel<<<dim3(H_DIM / 128, 32, E_NUM), 256, SMEM_BYTES>>>(b2, out);
}

// round 7
// speedup vs baseline: 1.2879x; 1.0023x over previous
#include <cuda_runtime.h>
#include <cuda_fp16.h>
#include <math.h>
#include <stdint.h>

#define T_TOK 4096
#define H_DIM 1024
#define E_NUM 8
#define F_DIM 4096

#define A_ST 5120            // 128*40 halfs per A stage
#define B_ST 4352            // 32*136 halfs per B stage
#define STAGES 4
#define SMEM_BYTES ((STAGES * (A_ST + B_ST)) * 2)   // 75776

// ---------------- scratch (static device globals; no allocations) ----------
__device__ int    g_cnt[E_NUM];
__device__ int    g_tok[E_NUM * T_TOK];
__device__ float  g_gate[E_NUM * T_TOK];
__device__ __half g_xh[(size_t)T_TOK * H_DIM];             // x fp16 (8 MB)
__device__ __half g_h[(size_t)T_TOK * 2 * F_DIM];          // routed hidden (64 MB)
__device__ __half g_w1[(size_t)E_NUM * H_DIM * F_DIM];     // W1 fp16 (64 MB)
__device__ __half g_w2[(size_t)E_NUM * F_DIM * H_DIM];     // W2 fp16 (64 MB)

// ---------------- helpers -------------------------------------------------
__device__ __forceinline__ float gelu_f(float v) {
    return 0.5f * v * (1.0f + erff(v * 0.70710678118654752440f));
}

__device__ __forceinline__ void mma16816(float* c, const unsigned* a, const unsigned* b) {
    asm volatile(
        "mma.sync.aligned.m16n8k16.row.col.f32.f16.f16.f32 "
        "{%0,%1,%2,%3}, {%4,%5,%6,%7}, {%8,%9}, {%0,%1,%2,%3};\n"
        : "+f"(c[0]), "+f"(c[1]), "+f"(c[2]), "+f"(c[3])
        : "r"(a[0]), "r"(a[1]), "r"(a[2]), "r"(a[3]), "r"(b[0]), "r"(b[1]));
}
__device__ __forceinline__ void ldsm_x4(unsigned* r, uint32_t addr) {
    asm volatile("ldmatrix.sync.aligned.m8n8.x4.shared.b16 {%0,%1,%2,%3}, [%4];\n"
                 : "=r"(r[0]), "=r"(r[1]), "=r"(r[2]), "=r"(r[3]) : "r"(addr));
}
__device__ __forceinline__ void ldsm_x4t(unsigned* r, uint32_t addr) {
    asm volatile("ldmatrix.sync.aligned.m8n8.x4.trans.shared.b16 {%0,%1,%2,%3}, [%4];\n"
                 : "=r"(r[0]), "=r"(r[1]), "=r"(r[2]), "=r"(r[3]) : "r"(addr));
}
__device__ __forceinline__ void cpa16(uint32_t dst, const void* src) {
    asm volatile("cp.async.cg.shared.global [%0], [%1], 16;\n" :: "r"(dst), "l"(src));
}
__device__ __forceinline__ void cpa16p(uint32_t dst, const void* src, bool valid) {
    int sz = valid ? 16 : 0;   // zero-fill when invalid
    asm volatile("cp.async.cg.shared.global [%0], [%1], 16, %2;\n"
                 :: "r"(dst), "l"(src), "r"(sz));
}
__device__ __forceinline__ void cpa_commit() { asm volatile("cp.async.commit_group;\n"); }
__device__ __forceinline__ void cpa_wait2()  { asm volatile("cp.async.wait_group 2;\n"); }

// ---------------- kernel 0: zero out + counters, convert x -> fp16 --------
__global__ void prep_kernel(const float* __restrict__ x, float* __restrict__ out) {
    int i = blockIdx.x * blockDim.x + threadIdx.x;
    if (i < T_TOK * H_DIM) {
        g_xh[i] = __float2half(x[i]);
        out[i]  = 0.0f;
    }
    if (i < E_NUM) g_cnt[i] = 0;
}

// ---------------- kernel 0b: convert W1/W2 -> fp16 ------------------------
__global__ void convw_kernel(const float* __restrict__ W1, const float* __restrict__ W2) {
    const size_t N = (size_t)E_NUM * H_DIM * F_DIM;
    size_t base = ((size_t)blockIdx.x * blockDim.x + threadIdx.x) * 8;
    if (base >= N) return;
    const float* src = blockIdx.y ? W2 : W1;
    __half* dst      = blockIdx.y ? g_w2 : g_w1;
    float4 a = *(const float4*)(src + base);
    float4 b = *(const float4*)(src + base + 4);
    __half2 h[4];
    h[0] = __floats2half2_rn(a.x, a.y);
    h[1] = __floats2half2_rn(a.z, a.w);
    h[2] = __floats2half2_rn(b.x, b.y);
    h[3] = __floats2half2_rn(b.z, b.w);
    *(uint4*)(dst + base) = *(uint4*)h;
}

// ---------------- kernel 1: router --------------------------------------
__global__ void router_kernel(const float* __restrict__ x, const float* __restrict__ Wr) {
    int gwarp = (blockIdx.x * blockDim.x + threadIdx.x) >> 5;
    int lane  = threadIdx.x & 31;
    if (gwarp >= T_TOK) return;
    const float* xr = x + (size_t)gwarp * H_DIM;
    float xv[32];
#pragma unroll
    for (int i = 0; i < 32; i++) xv[i] = xr[lane + 32 * i];

    float logits[E_NUM];
#pragma unroll
    for (int e = 0; e < E_NUM; e++) {
        const float* w = Wr + e * H_DIM;
        float s = 0.0f;
#pragma unroll
        for (int i = 0; i < 32; i++) s += xv[i] * w[lane + 32 * i];
#pragma unroll
        for (int o = 16; o > 0; o >>= 1) s += __shfl_xor_sync(0xffffffffu, s, o);
        logits[e] = s;
    }
    if (lane == 0) {
        int i0 = 0; float v0 = logits[0];
#pragma unroll
        for (int e = 1; e < E_NUM; e++) if (logits[e] > v0) { v0 = logits[e]; i0 = e; }
        int i1 = -1; float v1 = -1e30f;
#pragma unroll
        for (int e = 0; e < E_NUM; e++) if (e != i0 && logits[e] > v1) { v1 = logits[e]; i1 = e; }
        float ex = expf(v1 - v0);
        float p0 = 1.0f / (1.0f + ex);
        float p1 = ex / (1.0f + ex);
        int pos0 = atomicAdd(&g_cnt[i0], 1);
        g_tok[i0 * T_TOK + pos0] = gwarp;  g_gate[i0 * T_TOK + pos0] = p0;
        int pos1 = atomicAdd(&g_cnt[i1], 1);
        g_tok[i1 * T_TOK + pos1] = gwarp;  g_gate[i1 * T_TOK + pos1] = p1;
    }
}

// ---------------- GEMM1: h = gelu(x @ W1[e] + b1[e]) ----------------------
// grid: (F/128, 32, E), block 256. BM=128 BN=128 BK=32, 4-stage cp.async.
__global__ __launch_bounds__(256, 2) void gemm1_kernel(const float* __restrict__ b1) {
    const int e   = blockIdx.z;
    const int cnt = g_cnt[e];
    const int m0  = blockIdx.y * 128;
    if (m0 >= cnt) return;
    const int n0 = blockIdx.x * 128;
    int roff = 0;
#pragma unroll
    for (int i = 0; i < E_NUM; i++) roff += (i < e) ? g_cnt[i] : 0;
    const __half* W = g_w1 + (size_t)e * H_DIM * F_DIM;

    const int tid = threadIdx.x, lane = tid & 31, warp = tid >> 5;
    const int wm = warp & 3, wn = warp >> 2;

    extern __shared__ __half sh[];
    __shared__ int toks[128];

    if (tid < 128) {
        int r = m0 + tid;
        toks[tid] = (r < cnt) ? g_tok[e * T_TOK + r] : -1;
    }
    __syncthreads();

    uint32_t asb = (uint32_t)__cvta_generic_to_shared(sh);
    uint32_t bsb = (uint32_t)__cvta_generic_to_shared(sh + STAGES * A_ST);

    auto load_tile = [&](int kt, int s) {
        int k0 = kt * 32;
#pragma unroll
        for (int p = 0; p < 2; p++) {   // A: 128x32 halfs
            int idx = p * 256 + tid;
            int r = idx >> 2, c = idx & 3;
            int tok = toks[r];
            const void* src = (tok >= 0) ? (const void*)(g_xh + (size_t)tok * H_DIM + k0 + c * 8)
                                         : (const void*)g_xh;
            cpa16p(asb + (uint32_t)(s * A_ST + r * 40 + c * 8) * 2u, src, tok >= 0);
        }
#pragma unroll
        for (int p = 0; p < 2; p++) {   // B: 32x128 halfs
            int idx = p * 256 + tid;
            int kr = idx >> 4, c = idx & 15;
            cpa16(bsb + (uint32_t)(s * B_ST + kr * 136 + c * 8) * 2u,
                  W + (size_t)(k0 + kr) * F_DIM + n0 + c * 8);
        }
    };

    float acc[2][8][4];
#pragma unroll
    for (int a = 0; a < 2; a++)
#pragma unroll
        for (int b = 0; b < 8; b++)
#pragma unroll
            for (int c = 0; c < 4; c++) acc[a][b][c] = 0.0f;

    load_tile(0, 0); cpa_commit();
    load_tile(1, 1); cpa_commit();
    load_tile(2, 2); cpa_commit();

    const int NT = H_DIM / 32;
    for (int kt = 0; kt < NT; kt++) {
        int s = kt % STAGES;
        cpa_wait2();
        __syncthreads();
        int nk = kt + 3;
        if (nk < NT) load_tile(nk, nk % STAGES);
        cpa_commit();

        uint32_t as = asb + (uint32_t)(s * A_ST) * 2u;
        uint32_t bs = bsb + (uint32_t)(s * B_ST) * 2u;
#pragma unroll
        for (int ks = 0; ks < 2; ks++) {
            unsigned af[2][4], bf[4][4];
#pragma unroll
            for (int mi = 0; mi < 2; mi++) {
                int row = wm * 32 + mi * 16 + (lane & 15);
                int col = ks * 16 + (lane >> 4) * 8;
                ldsm_x4(af[mi], as + (uint32_t)(row * 40 + col) * 2u);
            }
#pragma unroll
            for (int nb = 0; nb < 4; nb++) {
                int kr  = ks * 16 + (lane & 15);
                int col = wn * 64 + nb * 16 + (lane >> 4) * 8;
                ldsm_x4t(bf[nb], bs + (uint32_t)(kr * 136 + col) * 2u);
            }
#pragma unroll
            for (int mi = 0; mi < 2; mi++)
#pragma unroll
                for (int nb = 0; nb < 4; nb++) {
                    mma16816(acc[mi][nb * 2],     af[mi], &bf[nb][0]);
                    mma16816(acc[mi][nb * 2 + 1], af[mi], &bf[nb][2]);
                }
        }
    }

    const float* be = b1 + e * F_DIM;
#pragma unroll
    for (int mi = 0; mi < 2; mi++) {
        int rbase = wm * 32 + mi * 16 + (lane >> 2);
#pragma unroll
        for (int nf = 0; nf < 8; nf++) {
            int cbase = wn * 64 + nf * 8 + (lane & 3) * 2;
#pragma unroll
            for (int h = 0; h < 2; h++) {
                int r = rbase + h * 8;
                int gm = m0 + r;
                if (gm < cnt) {
                    float v0 = gelu_f(acc[mi][nf][h * 2]     + be[n0 + cbase]);
                    float v1 = gelu_f(acc[mi][nf][h * 2 + 1] + be[n0 + cbase + 1]);
                    *(__half2*)(g_h + (size_t)(roff + gm) * F_DIM + n0 + cbase) =
                        __floats2half2_rn(v0, v1);
                }
            }
        }
    }
}

// ---------------- GEMM2: out[tok] += gate * (h @ W2[e] + b2[e]) -----------
// grid: (H/128, 32, E), block 256, 4-stage cp.async.
__global__ __launch_bounds__(256, 2) void gemm2_kernel(const float* __restrict__ b2,
                                                       float* __restrict__ out) {
    const int e   = blockIdx.z;
    const int cnt = g_cnt[e];
    const int m0  = blockIdx.y * 128;
    if (m0 >= cnt) return;
    const int n0 = blockIdx.x * 128;
    int roff = 0;
#pragma unroll
    for (int i = 0; i < E_NUM; i++) roff += (i < e) ? g_cnt[i] : 0;
    const __half* W = g_w2 + (size_t)e * F_DIM * H_DIM;

    const int tid = threadIdx.x, lane = tid & 31, warp = tid >> 5;
    const int wm = warp & 3, wn = warp >> 2;

    extern __shared__ __half sh[];
    __shared__ int   toks[128];
    __shared__ float gts[128];

    if (tid < 128) {
        int r = m0 + tid;
        if (r < cnt) { toks[tid] = g_tok[e * T_TOK + r]; gts[tid] = g_gate[e * T_TOK + r]; }
        else         { toks[tid] = 0;                    gts[tid] = 0.0f; }
    }
    __syncthreads();

    uint32_t asb = (uint32_t)__cvta_generic_to_shared(sh);
    uint32_t bsb = (uint32_t)__cvta_generic_to_shared(sh + STAGES * A_ST);

    auto load_tile = [&](int kt, int s) {
        int k0 = kt * 32;
#pragma unroll
        for (int p = 0; p < 2; p++) {
            int idx = p * 256 + tid;
            int r = idx >> 2, c = idx & 3;
            int gm = m0 + r;
            size_t srow = (size_t)roff + (gm < cnt ? gm : 0);
            cpa16(asb + (uint32_t)(s * A_ST + r * 40 + c * 8) * 2u,
                  g_h + srow * F_DIM + k0 + c * 8);
        }
#pragma unroll
        for (int p = 0; p < 2; p++) {
            int idx = p * 256 + tid;
            int kr = idx >> 4, c = idx & 15;
            cpa16(bsb + (uint32_t)(s * B_ST + kr * 136 + c * 8) * 2u,
                  W + (size_t)(k0 + kr) * H_DIM + n0 + c * 8);
        }
    };

    float acc[2][8][4];
#pragma unroll
    for (int a = 0; a < 2; a++)
#pragma unroll
        for (int b = 0; b < 8; b++)
#pragma unroll
            for (int c = 0; c < 4; c++) acc[a][b][c] = 0.0f;

    load_tile(0, 0); cpa_commit();
    load_tile(1, 1); cpa_commit();
    load_tile(2, 2); cpa_commit();

    const int NT = F_DIM / 32;
    for (int kt = 0; kt < NT; kt++) {
        int s = kt % STAGES;
        cpa_wait2();
        __syncthreads();
        int nk = kt + 3;
        if (nk < NT) load_tile(nk, nk % STAGES);
        cpa_commit();

        uint32_t as = asb + (uint32_t)(s * A_ST) * 2u;
        uint32_t bs = bsb + (uint32_t)(s * B_ST) * 2u;
#pragma unroll
        for (int ks = 0; ks < 2; ks++) {
            unsigned af[2][4], bf[4][4];
#pragma unroll
            for (int mi = 0; mi < 2; mi++) {
                int row = wm * 32 + mi * 16 + (lane & 15);
                int col = ks * 16 + (lane >> 4) * 8;
                ldsm_x4(af[mi], as + (uint32_t)(row * 40 + col) * 2u);
            }
#pragma unroll
            for (int nb = 0; nb < 4; nb++) {
                int kr  = ks * 16 + (lane & 15);
                int col = wn * 64 + nb * 16 + (lane >> 4) * 8;
                ldsm_x4t(bf[nb], bs + (uint32_t)(kr * 136 + col) * 2u);
            }
#pragma unroll
            for (int mi = 0; mi < 2; mi++)
#pragma unroll
                for (int nb = 0; nb < 4; nb++) {
                    mma16816(acc[mi][nb * 2],     af[mi], &bf[nb][0]);
                    mma16816(acc[mi][nb * 2 + 1], af[mi], &bf[nb][2]);
                }
        }
    }

    const float* be = b2 + e * H_DIM;
#pragma unroll
    for (int mi = 0; mi < 2; mi++) {
        int rbase = wm * 32 + mi * 16 + (lane >> 2);
#pragma unroll
        for (int nf = 0; nf < 8; nf++) {
            int cbase = wn * 64 + nf * 8 + (lane & 3) * 2;
#pragma unroll
            for (int h = 0; h < 2; h++) {
                int r = rbase + h * 8;
                int gm = m0 + r;
                if (gm < cnt) {
                    int   tok = toks[r];
                    float g   = gts[r];
                    float v0  = acc[mi][nf][h * 2]     + be[n0 + cbase];
                    float v1  = acc[mi][nf][h * 2 + 1] + be[n0 + cbase + 1];
                    atomicAdd(&out[(size_t)tok * H_DIM + n0 + cbase],     g * v0);
                    atomicAdd(&out[(size_t)tok * H_DIM + n0 + cbase + 1], g * v1);
                }
            }
        }
    }
}

// ---------------- launch ---------------------------------------------------
extern "C" void kernel_launch(void* const* d_in, const int* in_sizes, int n_in,
                              void* d_out, int out_size) {
    const float* x  = (const float*)d_in[0];
    const float* Wr = (const float*)d_in[1];
    const float* W1 = (const float*)d_in[2];
    const float* b1 = (const float*)d_in[3];
    const float* W2 = (const float*)d_in[4];
    const float* b2 = (const float*)d_in[5];
    float* out = (float*)d_out;

    cudaFuncSetAttribute(gemm1_kernel, cudaFuncAttributeMaxDynamicSharedMemorySize, SMEM_BYTES);
    cudaFuncSetAttribute(gemm2_kernel, cudaFuncAttributeMaxDynamicSharedMemorySize, SMEM_BYTES);

    prep_kernel<<<(T_TOK * H_DIM + 255) / 256, 256>>>(x, out);
    convw_kernel<<<dim3(16384, 2), 256>>>(W1, W2);
    router_kernel<<<T_TOK / 8, 256>>>(x, Wr);
    gemm1_kernel<<<dim3(F_DIM / 128, 32, E_NUM), 256, SMEM_BYTES>>>(b1);
    gemm2_kernel<<<dim3(H_DIM / 128, 32, E_NUM), 256, SMEM_BYTES>>>(b2, out);
}